// round 8
// baseline (speedup 1.0000x reference)
#include <cuda_runtime.h>
#include <cuda_bf16.h>
#include <cstdint>
#include <cstddef>

// ============================================================================
// SecureFeedForward: out = relu(X @ W1^T + b1) @ W2^T + b2
//   X [16384,1024] f32, W1 [4096,1024], W2 [1024,4096]
// bf16 hi/lo 3-pass split GEMMs on mma.sync (HMMA), fp32 accum.
// R7: 3-stage cp.async pipeline (single sync/iter) + pass-major MMA order.
// ============================================================================

static constexpr int HIDDEN = 1024;
static constexpr int INTER  = 4096;
static constexpr int MTOT   = 16384;

static constexpr int BM = 128;
static constexpr int BN = 128;
static constexpr int BK = 64;          // 128 bytes per smem row (SW128 atom)
static constexpr int THREADS = 256;    // 8 warps: 2 x 4, warp tile 64x32
static constexpr int STAGES = 3;

static constexpr int TILE_BYTES  = BM * BK * 2;      // 16384 per matrix
static constexpr int OFF_AHI = 0;
static constexpr int OFF_ALO = TILE_BYTES;
static constexpr int OFF_BHI = 2 * TILE_BYTES;
static constexpr int OFF_BLO = 3 * TILE_BYTES;
static constexpr int STAGE_BYTES = 4 * TILE_BYTES;        // 65536
static constexpr int SMEM_TOTAL  = STAGES * STAGE_BYTES;  // 196608

// ---- scratch (device globals: allocation-free rule) ----
__device__ __align__(128) __nv_bfloat16 g_xhi[(size_t)MTOT * HIDDEN];
__device__ __align__(128) __nv_bfloat16 g_xlo[(size_t)MTOT * HIDDEN];
__device__ __align__(128) __nv_bfloat16 g_w1hi[(size_t)INTER * HIDDEN];
__device__ __align__(128) __nv_bfloat16 g_w1lo[(size_t)INTER * HIDDEN];
__device__ __align__(128) __nv_bfloat16 g_w2hi[(size_t)HIDDEN * INTER];
__device__ __align__(128) __nv_bfloat16 g_w2lo[(size_t)HIDDEN * INTER];
__device__ __align__(128) __nv_bfloat16 g_ahi[(size_t)MTOT * INTER];
__device__ __align__(128) __nv_bfloat16 g_alo[(size_t)MTOT * INTER];

#define DEVINL __device__ __forceinline__

DEVINL uint32_t smem_u32(const void* p) {
    uint32_t a;
    asm("{ .reg .u64 t; cvta.to.shared.u64 t, %1; cvt.u32.u64 %0, t; }" : "=r"(a) : "l"(p));
    return a;
}
DEVINL uint32_t swz(uint32_t off) { return off ^ ((off >> 3) & 0x70); }  // SW128

DEVINL void cp16(uint32_t dst, const void* src) {
    asm volatile("cp.async.cg.shared.global [%0], [%1], 16;" :: "r"(dst), "l"(src));
}
DEVINL void cp_commit() { asm volatile("cp.async.commit_group;"); }
template <int N> DEVINL void cp_wait() { asm volatile("cp.async.wait_group %0;" :: "n"(N)); }

DEVINL void ldsm4(uint32_t* r, uint32_t addr) {
    asm volatile("ldmatrix.sync.aligned.m8n8.x4.shared.b16 {%0,%1,%2,%3}, [%4];"
                 : "=r"(r[0]), "=r"(r[1]), "=r"(r[2]), "=r"(r[3]) : "r"(addr));
}
DEVINL void mma_bf16(float* c, const uint32_t* a, const uint32_t* b) {
    asm volatile(
        "mma.sync.aligned.m16n8k16.row.col.f32.bf16.bf16.f32 "
        "{%0,%1,%2,%3}, {%4,%5,%6,%7}, {%8,%9}, {%0,%1,%2,%3};"
        : "+f"(c[0]), "+f"(c[1]), "+f"(c[2]), "+f"(c[3])
        : "r"(a[0]), "r"(a[1]), "r"(a[2]), "r"(a[3]), "r"(b[0]), "r"(b[1]));
}
DEVINL uint32_t pack2(__nv_bfloat16 a, __nv_bfloat16 b) {
    return (uint32_t)__bfloat16_as_ushort(a) | ((uint32_t)__bfloat16_as_ushort(b) << 16);
}

// ============================================================================
// fp32 -> bf16 hi/lo split (vectorized x4)
// ============================================================================
__global__ void split_kernel(const float4* __restrict__ src,
                             uint2* __restrict__ hi, uint2* __restrict__ lo, int n4) {
    int i = blockIdx.x * blockDim.x + threadIdx.x;
    if (i >= n4) return;
    float4 v = src[i];
    __nv_bfloat16 h0 = __float2bfloat16(v.x), h1 = __float2bfloat16(v.y);
    __nv_bfloat16 h2 = __float2bfloat16(v.z), h3 = __float2bfloat16(v.w);
    __nv_bfloat16 l0 = __float2bfloat16(v.x - __bfloat162float(h0));
    __nv_bfloat16 l1 = __float2bfloat16(v.y - __bfloat162float(h1));
    __nv_bfloat16 l2 = __float2bfloat16(v.z - __bfloat162float(h2));
    __nv_bfloat16 l3 = __float2bfloat16(v.w - __bfloat162float(h3));
    hi[i] = make_uint2(pack2(h0, h1), pack2(h2, h3));
    lo[i] = make_uint2(pack2(l0, l1), pack2(l2, l3));
}

// ============================================================================
// GEMM: D[BM,BN] = A[BM,K] @ B[BN,K]^T (3-pass hi/lo), fused epilogue
//   MODE 1: +bias, relu, write bf16 hi/lo (stride INTER)
//   MODE 2: +bias, write fp32 (stride HIDDEN)
// ============================================================================
template <int KD, int MODE>
__global__ void __launch_bounds__(THREADS, 1)
ffn_gemm(const __nv_bfloat16* __restrict__ Ahi, const __nv_bfloat16* __restrict__ Alo,
         const __nv_bfloat16* __restrict__ Bhi, const __nv_bfloat16* __restrict__ Blo,
         const float* __restrict__ bias,
         __nv_bfloat16* __restrict__ Ohi, __nv_bfloat16* __restrict__ Olo,
         float* __restrict__ Of) {
    extern __shared__ __align__(1024) char smem[];
    const uint32_t sb = smem_u32(smem);
    const int tid  = threadIdx.x;
    const int wid  = tid >> 5;
    const int lane = tid & 31;
    const int m0 = blockIdx.y * BM;
    const int n0 = blockIdx.x * BN;
    const int warp_m = (wid >> 2) * 64;   // 2 warp rows
    const int warp_n = (wid & 3) * 32;    // 4 warp cols
    constexpr int NK = KD / BK;

    // ---- chunk loader: 4096 x 16B granules, 16 per thread, SW128 swizzle ----
    auto load_chunk = [&](int kc, int stg) {
        const uint32_t base = sb + (uint32_t)stg * STAGE_BYTES;
        const int kofs = kc * BK;
#pragma unroll
        for (int t = 0; t < 16; ++t) {
            const int mat = t >> 2;                 // 0:AHI 1:ALO 2:BHI 3:BLO
            const int gg  = (t & 3) * 256 + tid;    // 0..1023
            const int row = gg >> 3, ch = gg & 7;
            const __nv_bfloat16* bp =
                (mat == 0) ? Ahi : (mat == 1) ? Alo : (mat == 2) ? Bhi : Blo;
            const int grow = ((mat < 2) ? m0 : n0) + row;
            const __nv_bfloat16* src = bp + (size_t)grow * KD + kofs + ch * 8;
            const uint32_t dst = base + (uint32_t)mat * TILE_BYTES +
                                 swz((uint32_t)(row * 128 + ch * 16));
            cp16(dst, src);
        }
        cp_commit();
    };

    float acc[4][4][4];
#pragma unroll
    for (int a = 0; a < 4; ++a)
#pragma unroll
        for (int b = 0; b < 4; ++b)
#pragma unroll
            for (int c = 0; c < 4; ++c) acc[a][b][c] = 0.0f;

    // ---- compute one 64-K chunk: 4 k16 steps, pass-major MMA ordering ----
    auto compute = [&](int stg) {
        const uint32_t base = sb + (uint32_t)stg * STAGE_BYTES;
#pragma unroll
        for (int kk = 0; kk < 4; ++kk) {
            const int k0 = kk * 16;
            uint32_t ah[4][4], al[4][4];
#pragma unroll
            for (int mt = 0; mt < 4; ++mt) {
                const int row = warp_m + mt * 16 + (lane & 15);
                const int kc_ = k0 + (lane >> 4) * 8;
                const uint32_t rel = (uint32_t)(row * 128 + kc_ * 2);
                ldsm4(ah[mt], base + OFF_AHI + swz(rel));
                ldsm4(al[mt], base + OFF_ALO + swz(rel));
            }
            uint32_t bh[2][4], bl[2][4];
#pragma unroll
            for (int nb = 0; nb < 2; ++nb) {
                const int nrow = warp_n + nb * 16 + ((lane >> 4) & 1) * 8 + (lane & 7);
                const int kcol = k0 + ((lane >> 3) & 1) * 8;
                const uint32_t rel = (uint32_t)(nrow * 128 + kcol * 2);
                ldsm4(bh[nb], base + OFF_BHI + swz(rel));
                ldsm4(bl[nb], base + OFF_BLO + swz(rel));
            }
            // pass-major: 16 independent MMAs between accumulator reuse
#pragma unroll
            for (int mt = 0; mt < 4; ++mt)
#pragma unroll
                for (int j = 0; j < 4; ++j)
                    mma_bf16(acc[mt][j], ah[mt], &bh[j >> 1][(j & 1) * 2]);
#pragma unroll
            for (int mt = 0; mt < 4; ++mt)
#pragma unroll
                for (int j = 0; j < 4; ++j)
                    mma_bf16(acc[mt][j], ah[mt], &bl[j >> 1][(j & 1) * 2]);
#pragma unroll
            for (int mt = 0; mt < 4; ++mt)
#pragma unroll
                for (int j = 0; j < 4; ++j)
                    mma_bf16(acc[mt][j], al[mt], &bh[j >> 1][(j & 1) * 2]);
        }
    };

    // ---- 3-stage pipelined mainloop, single sync per iteration ----
    // Invariant at iter kc top: stages hold kc (wait), kc+1 (in flight).
    // After the sync (all warps done compute(kc-1)), stage (kc+2)%3 ==
    // (kc-1)%3 is free -> issue its load BEFORE compute so cp.async overlaps MMAs.
    load_chunk(0, 0);
    load_chunk(1, 1);
    int cur = 0, ldst = 2;
    for (int kc = 0; kc < NK; ++kc) {
        if (kc + 1 < NK) cp_wait<1>(); else cp_wait<0>();
        __syncthreads();
        if (kc + 2 < NK) load_chunk(kc + 2, ldst);
        compute(cur);
        cur  = (cur  == STAGES - 1) ? 0 : cur + 1;
        ldst = (ldst == STAGES - 1) ? 0 : ldst + 1;
    }

    // ---- epilogue (register fragments -> gmem) ----
#pragma unroll
    for (int mt = 0; mt < 4; ++mt)
#pragma unroll
        for (int j = 0; j < 4; ++j) {
            const int n = n0 + warp_n + j * 8 + (lane & 3) * 2;
            const float bv0 = __ldg(&bias[n]);
            const float bv1 = __ldg(&bias[n + 1]);
#pragma unroll
            for (int h = 0; h < 2; ++h) {
                const int m = m0 + warp_m + mt * 16 + h * 8 + (lane >> 2);
                float v0 = acc[mt][j][2 * h + 0] + bv0;
                float v1 = acc[mt][j][2 * h + 1] + bv1;
                if (MODE == 1) {
                    v0 = fmaxf(v0, 0.0f);
                    v1 = fmaxf(v1, 0.0f);
                    __nv_bfloat16 h0 = __float2bfloat16(v0), h1 = __float2bfloat16(v1);
                    __nv_bfloat16 l0 = __float2bfloat16(v0 - __bfloat162float(h0));
                    __nv_bfloat16 l1 = __float2bfloat16(v1 - __bfloat162float(h1));
                    const size_t o = (size_t)m * INTER + n;
                    *reinterpret_cast<uint32_t*>(Ohi + o) = pack2(h0, h1);
                    *reinterpret_cast<uint32_t*>(Olo + o) = pack2(l0, l1);
                } else {
                    const size_t o = (size_t)m * HIDDEN + n;
                    float2 v; v.x = v0; v.y = v1;
                    *reinterpret_cast<float2*>(Of + o) = v;
                }
            }
        }
}

// ============================================================================
// Launch
// ============================================================================
extern "C" void kernel_launch(void* const* d_in, const int* in_sizes, int n_in,
                              void* d_out, int out_size) {
    const float* x  = (const float*)d_in[0];
    const float* W1 = (const float*)d_in[1];
    const float* b1 = (const float*)d_in[2];
    const float* W2 = (const float*)d_in[3];
    const float* b2 = (const float*)d_in[4];
    float* out = (float*)d_out;

    void *xhi, *xlo, *w1hi, *w1lo, *w2hi, *w2lo, *ahi, *alo;
    cudaGetSymbolAddress(&xhi, g_xhi);   cudaGetSymbolAddress(&xlo, g_xlo);
    cudaGetSymbolAddress(&w1hi, g_w1hi); cudaGetSymbolAddress(&w1lo, g_w1lo);
    cudaGetSymbolAddress(&w2hi, g_w2hi); cudaGetSymbolAddress(&w2lo, g_w2lo);
    cudaGetSymbolAddress(&ahi, g_ahi);   cudaGetSymbolAddress(&alo, g_alo);

    cudaFuncSetAttribute(ffn_gemm<HIDDEN, 1>, cudaFuncAttributeMaxDynamicSharedMemorySize, SMEM_TOTAL);
    cudaFuncSetAttribute(ffn_gemm<INTER, 2>,  cudaFuncAttributeMaxDynamicSharedMemorySize, SMEM_TOTAL);

    int n4;
    n4 = MTOT * HIDDEN / 4;
    split_kernel<<<(n4 + 255) / 256, 256>>>((const float4*)x, (uint2*)xhi, (uint2*)xlo, n4);
    n4 = INTER * HIDDEN / 4;
    split_kernel<<<(n4 + 255) / 256, 256>>>((const float4*)W1, (uint2*)w1hi, (uint2*)w1lo, n4);
    n4 = HIDDEN * INTER / 4;
    split_kernel<<<(n4 + 255) / 256, 256>>>((const float4*)W2, (uint2*)w2hi, (uint2*)w2lo, n4);

    ffn_gemm<HIDDEN, 1><<<dim3(INTER / BN, MTOT / BM), THREADS, SMEM_TOTAL>>>(
        (const __nv_bfloat16*)xhi, (const __nv_bfloat16*)xlo,
        (const __nv_bfloat16*)w1hi, (const __nv_bfloat16*)w1lo,
        b1, (__nv_bfloat16*)ahi, (__nv_bfloat16*)alo, nullptr);

    ffn_gemm<INTER, 2><<<dim3(HIDDEN / BN, MTOT / BM), THREADS, SMEM_TOTAL>>>(
        (const __nv_bfloat16*)ahi, (const __nv_bfloat16*)alo,
        (const __nv_bfloat16*)w2hi, (const __nv_bfloat16*)w2lo,
        b2, nullptr, nullptr, out);
}

// round 11
// speedup vs baseline: 1.5543x; 1.5543x over previous
#include <cuda_runtime.h>
#include <cuda_bf16.h>
#include <cstdint>
#include <cstddef>

// ============================================================================
// SecureFeedForward: out = relu(X @ W1^T + b1) @ W2^T + b2
//   X [16384,1024] f32, W1 [4096,1024], W2 [1024,4096]
// bf16 hi/lo 3-pass split GEMMs on mma.sync (HMMA), fp32 accum.
// R9: R6 loop structure (proven), BN=64 + 2 CTAs/SM for latency hiding.
// ============================================================================

static constexpr int HIDDEN = 1024;
static constexpr int INTER  = 4096;
static constexpr int MTOT   = 16384;

static constexpr int BM = 128;
static constexpr int BN = 64;
static constexpr int BK = 64;          // 128 bytes per smem row (SW128 atom)
static constexpr int THREADS = 256;    // 8 warps: 4 x 2, warp tile 32x32

static constexpr int A_BYTES = BM * BK * 2;   // 16384 per A matrix
static constexpr int B_BYTES = BN * BK * 2;   // 8192 per B matrix
static constexpr int OFF_AHI = 0;
static constexpr int OFF_ALO = A_BYTES;
static constexpr int OFF_BHI = 2 * A_BYTES;
static constexpr int OFF_BLO = 2 * A_BYTES + B_BYTES;
static constexpr int STAGE_BYTES = 2 * A_BYTES + 2 * B_BYTES;  // 49152
static constexpr int SMEM_TOTAL  = 2 * STAGE_BYTES;            // 98304 (2 stages)

// ---- scratch (device globals: allocation-free rule) ----
__device__ __align__(128) __nv_bfloat16 g_xhi[(size_t)MTOT * HIDDEN];
__device__ __align__(128) __nv_bfloat16 g_xlo[(size_t)MTOT * HIDDEN];
__device__ __align__(128) __nv_bfloat16 g_w1hi[(size_t)INTER * HIDDEN];
__device__ __align__(128) __nv_bfloat16 g_w1lo[(size_t)INTER * HIDDEN];
__device__ __align__(128) __nv_bfloat16 g_w2hi[(size_t)HIDDEN * INTER];
__device__ __align__(128) __nv_bfloat16 g_w2lo[(size_t)HIDDEN * INTER];
__device__ __align__(128) __nv_bfloat16 g_ahi[(size_t)MTOT * INTER];
__device__ __align__(128) __nv_bfloat16 g_alo[(size_t)MTOT * INTER];

#define DEVINL __device__ __forceinline__

DEVINL uint32_t smem_u32(const void* p) {
    uint32_t a;
    asm("{ .reg .u64 t; cvta.to.shared.u64 t, %1; cvt.u32.u64 %0, t; }" : "=r"(a) : "l"(p));
    return a;
}
DEVINL uint32_t swz(uint32_t off) { return off ^ ((off >> 3) & 0x70); }  // SW128

DEVINL void cp16(uint32_t dst, const void* src) {
    asm volatile("cp.async.cg.shared.global [%0], [%1], 16;" :: "r"(dst), "l"(src));
}
DEVINL void cp_commit() { asm volatile("cp.async.commit_group;"); }
template <int N> DEVINL void cp_wait() { asm volatile("cp.async.wait_group %0;" :: "n"(N)); }

DEVINL void ldsm4(uint32_t* r, uint32_t addr) {
    asm volatile("ldmatrix.sync.aligned.m8n8.x4.shared.b16 {%0,%1,%2,%3}, [%4];"
                 : "=r"(r[0]), "=r"(r[1]), "=r"(r[2]), "=r"(r[3]) : "r"(addr));
}
DEVINL void mma_bf16(float* c, const uint32_t* a, const uint32_t* b) {
    asm volatile(
        "mma.sync.aligned.m16n8k16.row.col.f32.bf16.bf16.f32 "
        "{%0,%1,%2,%3}, {%4,%5,%6,%7}, {%8,%9}, {%0,%1,%2,%3};"
        : "+f"(c[0]), "+f"(c[1]), "+f"(c[2]), "+f"(c[3])
        : "r"(a[0]), "r"(a[1]), "r"(a[2]), "r"(a[3]), "r"(b[0]), "r"(b[1]));
}
DEVINL uint32_t pack2(__nv_bfloat16 a, __nv_bfloat16 b) {
    return (uint32_t)__bfloat16_as_ushort(a) | ((uint32_t)__bfloat16_as_ushort(b) << 16);
}

// ============================================================================
// fp32 -> bf16 hi/lo split (vectorized x4)
// ============================================================================
__global__ void split_kernel(const float4* __restrict__ src,
                             uint2* __restrict__ hi, uint2* __restrict__ lo, int n4) {
    int i = blockIdx.x * blockDim.x + threadIdx.x;
    if (i >= n4) return;
    float4 v = src[i];
    __nv_bfloat16 h0 = __float2bfloat16(v.x), h1 = __float2bfloat16(v.y);
    __nv_bfloat16 h2 = __float2bfloat16(v.z), h3 = __float2bfloat16(v.w);
    __nv_bfloat16 l0 = __float2bfloat16(v.x - __bfloat162float(h0));
    __nv_bfloat16 l1 = __float2bfloat16(v.y - __bfloat162float(h1));
    __nv_bfloat16 l2 = __float2bfloat16(v.z - __bfloat162float(h2));
    __nv_bfloat16 l3 = __float2bfloat16(v.w - __bfloat162float(h3));
    hi[i] = make_uint2(pack2(h0, h1), pack2(h2, h3));
    lo[i] = make_uint2(pack2(l0, l1), pack2(l2, l3));
}

// ============================================================================
// GEMM: D[BM,BN] = A[BM,K] @ B[BN,K]^T (3-pass hi/lo), fused epilogue
//   MODE 1: +bias, relu, write bf16 hi/lo (stride INTER)
//   MODE 2: +bias, write fp32 (stride HIDDEN)
// ============================================================================
template <int KD, int MODE>
__global__ void __launch_bounds__(THREADS, 2)
ffn_gemm(const __nv_bfloat16* __restrict__ Ahi, const __nv_bfloat16* __restrict__ Alo,
         const __nv_bfloat16* __restrict__ Bhi, const __nv_bfloat16* __restrict__ Blo,
         const float* __restrict__ bias,
         __nv_bfloat16* __restrict__ Ohi, __nv_bfloat16* __restrict__ Olo,
         float* __restrict__ Of) {
    extern __shared__ __align__(1024) char smem[];
    const uint32_t sb = smem_u32(smem);
    const int tid  = threadIdx.x;
    const int wid  = tid >> 5;
    const int lane = tid & 31;
    const int m0 = blockIdx.y * BM;
    const int n0 = blockIdx.x * BN;
    const int warp_m = (wid >> 1) * 32;   // 4 warp rows
    const int warp_n = (wid & 1) * 32;    // 2 warp cols
    constexpr int NK = KD / BK;

    // ---- chunk loader: 3072 x 16B granules, 12 per thread, SW128 swizzle ----
    auto load_chunk = [&](int kc, int stg) {
        const uint32_t base = sb + (uint32_t)stg * STAGE_BYTES;
        const int kofs = kc * BK;
#pragma unroll
        for (int t = 0; t < 12; ++t) {
            const __nv_bfloat16* bp;
            uint32_t moff;
            int gg, grow;
            if (t < 8) {            // A hi (t<4) / A lo: 1024 granules each
                gg = (t & 3) * 256 + tid;
                bp = (t < 4) ? Ahi : Alo;
                moff = (t < 4) ? OFF_AHI : OFF_ALO;
                grow = m0 + (gg >> 3);
            } else {                // B hi (t<10) / B lo: 512 granules each
                gg = (t & 1) * 256 + tid;
                bp = (t < 10) ? Bhi : Blo;
                moff = (t < 10) ? OFF_BHI : OFF_BLO;
                grow = n0 + (gg >> 3);
            }
            const int ch = gg & 7;
            const int row = gg >> 3;
            const __nv_bfloat16* src = bp + (size_t)grow * KD + kofs + ch * 8;
            const uint32_t dst = base + moff + swz((uint32_t)(row * 128 + ch * 16));
            cp16(dst, src);
        }
        cp_commit();
    };

    float acc[2][4][4];
#pragma unroll
    for (int a = 0; a < 2; ++a)
#pragma unroll
        for (int b = 0; b < 4; ++b)
#pragma unroll
            for (int c = 0; c < 4; ++c) acc[a][b][c] = 0.0f;

    // ---- compute one 64-K chunk: 4 k16 steps, pass-major MMA ordering ----
    auto compute = [&](int stg) {
        const uint32_t base = sb + (uint32_t)stg * STAGE_BYTES;
#pragma unroll
        for (int kk = 0; kk < 4; ++kk) {
            const int k0 = kk * 16;
            uint32_t ah[2][4], al[2][4];
#pragma unroll
            for (int mt = 0; mt < 2; ++mt) {
                const int row = warp_m + mt * 16 + (lane & 15);
                const int kc_ = k0 + (lane >> 4) * 8;
                const uint32_t rel = (uint32_t)(row * 128 + kc_ * 2);
                ldsm4(ah[mt], base + OFF_AHI + swz(rel));
                ldsm4(al[mt], base + OFF_ALO + swz(rel));
            }
            uint32_t bh[2][4], bl[2][4];
#pragma unroll
            for (int nb = 0; nb < 2; ++nb) {
                const int nrow = warp_n + nb * 16 + ((lane >> 4) & 1) * 8 + (lane & 7);
                const int kcol = k0 + ((lane >> 3) & 1) * 8;
                const uint32_t rel = (uint32_t)(nrow * 128 + kcol * 2);
                ldsm4(bh[nb], base + OFF_BHI + swz(rel));
                ldsm4(bl[nb], base + OFF_BLO + swz(rel));
            }
            // pass-major: 8 independent MMAs between accumulator reuse
#pragma unroll
            for (int mt = 0; mt < 2; ++mt)
#pragma unroll
                for (int j = 0; j < 4; ++j)
                    mma_bf16(acc[mt][j], ah[mt], &bh[j >> 1][(j & 1) * 2]);
#pragma unroll
            for (int mt = 0; mt < 2; ++mt)
#pragma unroll
                for (int j = 0; j < 4; ++j)
                    mma_bf16(acc[mt][j], ah[mt], &bl[j >> 1][(j & 1) * 2]);
#pragma unroll
            for (int mt = 0; mt < 2; ++mt)
#pragma unroll
                for (int j = 0; j < 4; ++j)
                    mma_bf16(acc[mt][j], al[mt], &bh[j >> 1][(j & 1) * 2]);
        }
    };

    // ---- double-buffered mainloop (R6 proven structure) ----
    load_chunk(0, 0);
    load_chunk(1, 1);
    for (int kc = 0; kc < NK; ++kc) {
        if (kc + 1 < NK) cp_wait<1>(); else cp_wait<0>();
        __syncthreads();
        compute(kc & 1);
        __syncthreads();
        if (kc + 2 < NK) load_chunk(kc + 2, kc & 1);
    }

    // ---- epilogue (register fragments -> gmem) ----
#pragma unroll
    for (int mt = 0; mt < 2; ++mt)
#pragma unroll
        for (int j = 0; j < 4; ++j) {
            const int n = n0 + warp_n + j * 8 + (lane & 3) * 2;
            const float bv0 = __ldg(&bias[n]);
            const float bv1 = __ldg(&bias[n + 1]);
#pragma unroll
            for (int h = 0; h < 2; ++h) {
                const int m = m0 + warp_m + mt * 16 + h * 8 + (lane >> 2);
                float v0 = acc[mt][j][2 * h + 0] + bv0;
                float v1 = acc[mt][j][2 * h + 1] + bv1;
                if (MODE == 1) {
                    v0 = fmaxf(v0, 0.0f);
                    v1 = fmaxf(v1, 0.0f);
                    __nv_bfloat16 h0 = __float2bfloat16(v0), h1 = __float2bfloat16(v1);
                    __nv_bfloat16 l0 = __float2bfloat16(v0 - __bfloat162float(h0));
                    __nv_bfloat16 l1 = __float2bfloat16(v1 - __bfloat162float(h1));
                    const size_t o = (size_t)m * INTER + n;
                    *reinterpret_cast<uint32_t*>(Ohi + o) = pack2(h0, h1);
                    *reinterpret_cast<uint32_t*>(Olo + o) = pack2(l0, l1);
                } else {
                    const size_t o = (size_t)m * HIDDEN + n;
                    float2 v; v.x = v0; v.y = v1;
                    *reinterpret_cast<float2*>(Of + o) = v;
                }
            }
        }
}

// ============================================================================
// Launch
// ============================================================================
extern "C" void kernel_launch(void* const* d_in, const int* in_sizes, int n_in,
                              void* d_out, int out_size) {
    const float* x  = (const float*)d_in[0];
    const float* W1 = (const float*)d_in[1];
    const float* b1 = (const float*)d_in[2];
    const float* W2 = (const float*)d_in[3];
    const float* b2 = (const float*)d_in[4];
    float* out = (float*)d_out;

    void *xhi, *xlo, *w1hi, *w1lo, *w2hi, *w2lo, *ahi, *alo;
    cudaGetSymbolAddress(&xhi, g_xhi);   cudaGetSymbolAddress(&xlo, g_xlo);
    cudaGetSymbolAddress(&w1hi, g_w1hi); cudaGetSymbolAddress(&w1lo, g_w1lo);
    cudaGetSymbolAddress(&w2hi, g_w2hi); cudaGetSymbolAddress(&w2lo, g_w2lo);
    cudaGetSymbolAddress(&ahi, g_ahi);   cudaGetSymbolAddress(&alo, g_alo);

    cudaFuncSetAttribute(ffn_gemm<HIDDEN, 1>, cudaFuncAttributeMaxDynamicSharedMemorySize, SMEM_TOTAL);
    cudaFuncSetAttribute(ffn_gemm<INTER, 2>,  cudaFuncAttributeMaxDynamicSharedMemorySize, SMEM_TOTAL);

    int n4;
    n4 = MTOT * HIDDEN / 4;
    split_kernel<<<(n4 + 255) / 256, 256>>>((const float4*)x, (uint2*)xhi, (uint2*)xlo, n4);
    n4 = INTER * HIDDEN / 4;
    split_kernel<<<(n4 + 255) / 256, 256>>>((const float4*)W1, (uint2*)w1hi, (uint2*)w1lo, n4);
    n4 = HIDDEN * INTER / 4;
    split_kernel<<<(n4 + 255) / 256, 256>>>((const float4*)W2, (uint2*)w2hi, (uint2*)w2lo, n4);

    ffn_gemm<HIDDEN, 1><<<dim3(INTER / BN, MTOT / BM), THREADS, SMEM_TOTAL>>>(
        (const __nv_bfloat16*)xhi, (const __nv_bfloat16*)xlo,
        (const __nv_bfloat16*)w1hi, (const __nv_bfloat16*)w1lo,
        b1, (__nv_bfloat16*)ahi, (__nv_bfloat16*)alo, nullptr);

    ffn_gemm<INTER, 2><<<dim3(HIDDEN / BN, MTOT / BM), THREADS, SMEM_TOTAL>>>(
        (const __nv_bfloat16*)ahi, (const __nv_bfloat16*)alo,
        (const __nv_bfloat16*)w2hi, (const __nv_bfloat16*)w2lo,
        b2, nullptr, nullptr, out);
}

// round 15
// speedup vs baseline: 2.1398x; 1.3767x over previous
#include <cuda_runtime.h>
#include <cuda_fp16.h>
#include <cstdint>
#include <cstddef>

// ============================================================================
// SecureFeedForward: out = relu(X @ W1^T + b1) @ W2^T + b2
//   X [16384,1024] f32, W1 [4096,1024], W2 [1024,4096]
// R12: fp16 hi/lo 2-pass GEMMs (D = Ahi*Bhi + Alo*Bhi, B rounded to fp16).
// Dropped-term error ~2^-11/sqrt(3) per GEMM -> ~4e-4 total (< 1e-3 gate).
// Loop/tile structure identical to R11 (proven: 2 CTAs/SM, 2-stage cp.async).
// ============================================================================

static constexpr int HIDDEN = 1024;
static constexpr int INTER  = 4096;
static constexpr int MTOT   = 16384;

static constexpr int BM = 128;
static constexpr int BN = 64;
static constexpr int BK = 64;          // 128 bytes per smem row (SW128 atom)
static constexpr int THREADS = 256;    // 8 warps: 4 x 2, warp tile 32x32

static constexpr int A_BYTES = BM * BK * 2;   // 16384 per A matrix
static constexpr int B_BYTES = BN * BK * 2;   // 8192
static constexpr int OFF_AHI = 0;
static constexpr int OFF_ALO = A_BYTES;
static constexpr int OFF_BHI = 2 * A_BYTES;
static constexpr int STAGE_BYTES = 2 * A_BYTES + B_BYTES;      // 40960
static constexpr int SMEM_TOTAL  = 2 * STAGE_BYTES;            // 81920 (2 stages)

// ---- scratch (device globals: allocation-free rule) ----
__device__ __align__(128) __half g_xhi[(size_t)MTOT * HIDDEN];
__device__ __align__(128) __half g_xlo[(size_t)MTOT * HIDDEN];
__device__ __align__(128) __half g_w1hi[(size_t)INTER * HIDDEN];
__device__ __align__(128) __half g_w2hi[(size_t)HIDDEN * INTER];
__device__ __align__(128) __half g_ahi[(size_t)MTOT * INTER];
__device__ __align__(128) __half g_alo[(size_t)MTOT * INTER];

#define DEVINL __device__ __forceinline__

DEVINL uint32_t smem_u32(const void* p) {
    uint32_t a;
    asm("{ .reg .u64 t; cvta.to.shared.u64 t, %1; cvt.u32.u64 %0, t; }" : "=r"(a) : "l"(p));
    return a;
}
DEVINL uint32_t swz(uint32_t off) { return off ^ ((off >> 3) & 0x70); }  // SW128

DEVINL void cp16(uint32_t dst, const void* src) {
    asm volatile("cp.async.cg.shared.global [%0], [%1], 16;" :: "r"(dst), "l"(src));
}
DEVINL void cp_commit() { asm volatile("cp.async.commit_group;"); }
template <int N> DEVINL void cp_wait() { asm volatile("cp.async.wait_group %0;" :: "n"(N)); }

DEVINL void ldsm4(uint32_t* r, uint32_t addr) {
    asm volatile("ldmatrix.sync.aligned.m8n8.x4.shared.b16 {%0,%1,%2,%3}, [%4];"
                 : "=r"(r[0]), "=r"(r[1]), "=r"(r[2]), "=r"(r[3]) : "r"(addr));
}
DEVINL void mma_f16(float* c, const uint32_t* a, const uint32_t* b) {
    asm volatile(
        "mma.sync.aligned.m16n8k16.row.col.f32.f16.f16.f32 "
        "{%0,%1,%2,%3}, {%4,%5,%6,%7}, {%8,%9}, {%0,%1,%2,%3};"
        : "+f"(c[0]), "+f"(c[1]), "+f"(c[2]), "+f"(c[3])
        : "r"(a[0]), "r"(a[1]), "r"(a[2]), "r"(a[3]), "r"(b[0]), "r"(b[1]));
}
DEVINL uint32_t pack2h(__half a, __half b) {
    return (uint32_t)__half_as_ushort(a) | ((uint32_t)__half_as_ushort(b) << 16);
}

// ============================================================================
// fp32 -> fp16 hi/lo split (vectorized x4)
// ============================================================================
__global__ void split_hl(const float4* __restrict__ src,
                         uint2* __restrict__ hi, uint2* __restrict__ lo, int n4) {
    int i = blockIdx.x * blockDim.x + threadIdx.x;
    if (i >= n4) return;
    float4 v = src[i];
    __half h0 = __float2half(v.x), h1 = __float2half(v.y);
    __half h2 = __float2half(v.z), h3 = __float2half(v.w);
    __half l0 = __float2half(v.x - __half2float(h0));
    __half l1 = __float2half(v.y - __half2float(h1));
    __half l2 = __float2half(v.z - __half2float(h2));
    __half l3 = __float2half(v.w - __half2float(h3));
    hi[i] = make_uint2(pack2h(h0, h1), pack2h(h2, h3));
    lo[i] = make_uint2(pack2h(l0, l1), pack2h(l2, l3));
}

// fp32 -> fp16 (hi only, for weights)
__global__ void split_h(const float4* __restrict__ src, uint2* __restrict__ hi, int n4) {
    int i = blockIdx.x * blockDim.x + threadIdx.x;
    if (i >= n4) return;
    float4 v = src[i];
    hi[i] = make_uint2(pack2h(__float2half(v.x), __float2half(v.y)),
                       pack2h(__float2half(v.z), __float2half(v.w)));
}

// ============================================================================
// GEMM: D[BM,BN] = (Ahi+Alo)[BM,K] @ Bhi[BN,K]^T (2-pass), fused epilogue
//   MODE 1: +bias, relu, write fp16 hi/lo (stride INTER)
//   MODE 2: +bias, write fp32 (stride HIDDEN)
// ============================================================================
template <int KD, int MODE>
__global__ void __launch_bounds__(THREADS, 2)
ffn_gemm(const __half* __restrict__ Ahi, const __half* __restrict__ Alo,
         const __half* __restrict__ Bhi,
         const float* __restrict__ bias,
         __half* __restrict__ Ohi, __half* __restrict__ Olo,
         float* __restrict__ Of) {
    extern __shared__ __align__(1024) char smem[];
    const uint32_t sb = smem_u32(smem);
    const int tid  = threadIdx.x;
    const int wid  = tid >> 5;
    const int lane = tid & 31;
    const int m0 = blockIdx.y * BM;
    const int n0 = blockIdx.x * BN;
    const int warp_m = (wid >> 1) * 32;   // 4 warp rows
    const int warp_n = (wid & 1) * 32;    // 2 warp cols
    constexpr int NK = KD / BK;

    // ---- chunk loader: 2560 x 16B granules, 10 per thread, SW128 swizzle ----
    auto load_chunk = [&](int kc, int stg) {
        const uint32_t base = sb + (uint32_t)stg * STAGE_BYTES;
        const int kofs = kc * BK;
#pragma unroll
        for (int t = 0; t < 10; ++t) {
            const __half* bp;
            uint32_t moff;
            int gg, grow;
            if (t < 8) {            // A hi (t<4) / A lo: 1024 granules each
                gg = (t & 3) * 256 + tid;
                bp = (t < 4) ? Ahi : Alo;
                moff = (t < 4) ? OFF_AHI : OFF_ALO;
                grow = m0 + (gg >> 3);
            } else {                // B hi: 512 granules
                gg = (t & 1) * 256 + tid;
                bp = Bhi;
                moff = OFF_BHI;
                grow = n0 + (gg >> 3);
            }
            const int ch = gg & 7;
            const int row = gg >> 3;
            const __half* src = bp + (size_t)grow * KD + kofs + ch * 8;
            const uint32_t dst = base + moff + swz((uint32_t)(row * 128 + ch * 16));
            cp16(dst, src);
        }
        cp_commit();
    };

    float acc[2][4][4];
#pragma unroll
    for (int a = 0; a < 2; ++a)
#pragma unroll
        for (int b = 0; b < 4; ++b)
#pragma unroll
            for (int c = 0; c < 4; ++c) acc[a][b][c] = 0.0f;

    // ---- compute one 64-K chunk: 4 k16 steps, pass-major MMA ordering ----
    auto compute = [&](int stg) {
        const uint32_t base = sb + (uint32_t)stg * STAGE_BYTES;
#pragma unroll
        for (int kk = 0; kk < 4; ++kk) {
            const int k0 = kk * 16;
            uint32_t ah[2][4], al[2][4];
#pragma unroll
            for (int mt = 0; mt < 2; ++mt) {
                const int row = warp_m + mt * 16 + (lane & 15);
                const int kc_ = k0 + (lane >> 4) * 8;
                const uint32_t rel = (uint32_t)(row * 128 + kc_ * 2);
                ldsm4(ah[mt], base + OFF_AHI + swz(rel));
                ldsm4(al[mt], base + OFF_ALO + swz(rel));
            }
            uint32_t bh[2][4];
#pragma unroll
            for (int nb = 0; nb < 2; ++nb) {
                const int nrow = warp_n + nb * 16 + ((lane >> 4) & 1) * 8 + (lane & 7);
                const int kcol = k0 + ((lane >> 3) & 1) * 8;
                const uint32_t rel = (uint32_t)(nrow * 128 + kcol * 2);
                ldsm4(bh[nb], base + OFF_BHI + swz(rel));
            }
            // pass-major: 8 independent MMAs between accumulator reuse
#pragma unroll
            for (int mt = 0; mt < 2; ++mt)
#pragma unroll
                for (int j = 0; j < 4; ++j)
                    mma_f16(acc[mt][j], ah[mt], &bh[j >> 1][(j & 1) * 2]);
#pragma unroll
            for (int mt = 0; mt < 2; ++mt)
#pragma unroll
                for (int j = 0; j < 4; ++j)
                    mma_f16(acc[mt][j], al[mt], &bh[j >> 1][(j & 1) * 2]);
        }
    };

    // ---- double-buffered mainloop (proven structure) ----
    load_chunk(0, 0);
    load_chunk(1, 1);
    for (int kc = 0; kc < NK; ++kc) {
        if (kc + 1 < NK) cp_wait<1>(); else cp_wait<0>();
        __syncthreads();
        compute(kc & 1);
        __syncthreads();
        if (kc + 2 < NK) load_chunk(kc + 2, kc & 1);
    }

    // ---- epilogue (register fragments -> gmem) ----
#pragma unroll
    for (int mt = 0; mt < 2; ++mt)
#pragma unroll
        for (int j = 0; j < 4; ++j) {
            const int n = n0 + warp_n + j * 8 + (lane & 3) * 2;
            const float bv0 = __ldg(&bias[n]);
            const float bv1 = __ldg(&bias[n + 1]);
#pragma unroll
            for (int h = 0; h < 2; ++h) {
                const int m = m0 + warp_m + mt * 16 + h * 8 + (lane >> 2);
                float v0 = acc[mt][j][2 * h + 0] + bv0;
                float v1 = acc[mt][j][2 * h + 1] + bv1;
                if (MODE == 1) {
                    v0 = fmaxf(v0, 0.0f);
                    v1 = fmaxf(v1, 0.0f);
                    __half h0 = __float2half(v0), h1 = __float2half(v1);
                    __half l0 = __float2half(v0 - __half2float(h0));
                    __half l1 = __float2half(v1 - __half2float(h1));
                    const size_t o = (size_t)m * INTER + n;
                    *reinterpret_cast<uint32_t*>(Ohi + o) = pack2h(h0, h1);
                    *reinterpret_cast<uint32_t*>(Olo + o) = pack2h(l0, l1);
                } else {
                    const size_t o = (size_t)m * HIDDEN + n;
                    float2 v; v.x = v0; v.y = v1;
                    *reinterpret_cast<float2*>(Of + o) = v;
                }
            }
        }
}

// ============================================================================
// Launch
// ============================================================================
extern "C" void kernel_launch(void* const* d_in, const int* in_sizes, int n_in,
                              void* d_out, int out_size) {
    const float* x  = (const float*)d_in[0];
    const float* W1 = (const float*)d_in[1];
    const float* b1 = (const float*)d_in[2];
    const float* W2 = (const float*)d_in[3];
    const float* b2 = (const float*)d_in[4];
    float* out = (float*)d_out;

    void *xhi, *xlo, *w1hi, *w2hi, *ahi, *alo;
    cudaGetSymbolAddress(&xhi, g_xhi);   cudaGetSymbolAddress(&xlo, g_xlo);
    cudaGetSymbolAddress(&w1hi, g_w1hi); cudaGetSymbolAddress(&w2hi, g_w2hi);
    cudaGetSymbolAddress(&ahi, g_ahi);   cudaGetSymbolAddress(&alo, g_alo);

    cudaFuncSetAttribute(ffn_gemm<HIDDEN, 1>, cudaFuncAttributeMaxDynamicSharedMemorySize, SMEM_TOTAL);
    cudaFuncSetAttribute(ffn_gemm<INTER, 2>,  cudaFuncAttributeMaxDynamicSharedMemorySize, SMEM_TOTAL);

    int n4;
    n4 = MTOT * HIDDEN / 4;
    split_hl<<<(n4 + 255) / 256, 256>>>((const float4*)x, (uint2*)xhi, (uint2*)xlo, n4);
    n4 = INTER * HIDDEN / 4;
    split_h<<<(n4 + 255) / 256, 256>>>((const float4*)W1, (uint2*)w1hi, n4);
    n4 = HIDDEN * INTER / 4;
    split_h<<<(n4 + 255) / 256, 256>>>((const float4*)W2, (uint2*)w2hi, n4);

    ffn_gemm<HIDDEN, 1><<<dim3(INTER / BN, MTOT / BM), THREADS, SMEM_TOTAL>>>(
        (const __half*)xhi, (const __half*)xlo, (const __half*)w1hi,
        b1, (__half*)ahi, (__half*)alo, nullptr);

    ffn_gemm<INTER, 2><<<dim3(HIDDEN / BN, MTOT / BM), THREADS, SMEM_TOTAL>>>(
        (const __half*)ahi, (const __half*)alo, (const __half*)w2hi,
        b2, nullptr, nullptr, out);
}